// round 12
// baseline (speedup 1.0000x reference)
#include <cuda_runtime.h>

#define NB 4
#define NUM_OP 6
#define LANG_DIM 256
#define NHIDDEN 128
#define HH 128
#define WW 128
#define HWSZ (HH * WW)        // 16384
#define NC 128
#define SEM_CH (NUM_OP + 2)   // 8

#define CCHUNK 16
#define TPB 512
#define GRID_X (HWSZ / 4 / TPB)     // 8
#define GRID_Z (NC / CCHUNK)        // 8   -> 256 blocks x 512 threads

__device__ float4 g_actv4[NB][NHIDDEN / 4];

__device__ __forceinline__ float dot4(float4 a, float4 b) {
    return a.x * b.x + a.y * b.y + a.z * b.z + a.w * b.w;
}

// ---------------------------------------------------------------------------
// K1: actv[b][n] = bs[n] + lang[b,:].Ws[n,:]  — 32 blocks x 256 threads.
// Block q, warp w: row n = 4q + (w>>1), batch pair b0 = (w&1)*2.
// Each block reads 4 KB of Ws (float4, coalesced); Ws read once chip-wide.
// ---------------------------------------------------------------------------
__global__ __launch_bounds__(256) void actv_kernel(
    const float* __restrict__ lang,
    const float* __restrict__ Ws, const float* __restrict__ bs) {
    const int warp = threadIdx.x >> 5;
    const int lane = threadIdx.x & 31;
    const int n  = 4 * blockIdx.x + (warp >> 1);
    const int b0 = (warp & 1) * 2;

    const float4* Ws4   = reinterpret_cast<const float4*>(Ws) + (size_t)n * (LANG_DIM / 4);
    const float4* lang4 = reinterpret_cast<const float4*>(lang);

    float p0 = 0.0f, p1 = 0.0f;
#pragma unroll
    for (int i = 0; i < 2; ++i) {
        const int idx = lane + 32 * i;
        const float4 wv = Ws4[idx];
        p0 += dot4(wv, lang4[(size_t)b0 * (LANG_DIM / 4) + idx]);
        p1 += dot4(wv, lang4[(size_t)(b0 + 1) * (LANG_DIM / 4) + idx]);
    }
#pragma unroll
    for (int off = 16; off > 0; off >>= 1) {
        p0 += __shfl_xor_sync(0xFFFFFFFFu, p0, off);
        p1 += __shfl_xor_sync(0xFFFFFFFFu, p1, off);
    }
    if (lane == 0) {
        const float bias = bs[n];
        reinterpret_cast<float*>(g_actv4[b0])[n]     = p0 + bias;
        reinterpret_cast<float*>(g_actv4[b0 + 1])[n] = p1 + bias;
    }
}

// ---------------------------------------------------------------------------
// K2: 512-thread blocks -> 8 KB contiguous DRAM span per channel-chunk.
// sem loads issued first, fold overlapped under their latency, then stream.
// Grid (8,4,8) = 256 blocks x 512 threads.
// ---------------------------------------------------------------------------
__global__ __launch_bounds__(TPB) void main_kernel(
    const float* __restrict__ x,
    const float* __restrict__ sem,
    const float* __restrict__ Wg, const float* __restrict__ bg,
    const float* __restrict__ Wb, const float* __restrict__ bb,
    const float* __restrict__ Wr, const float* __restrict__ br,
    float* __restrict__ out) {
    const int tid  = threadIdx.x;
    const int warp = tid >> 5;
    const int lane = tid & 31;
    const int b    = blockIdx.y;
    const int c0   = blockIdx.z * CCHUNK;
    const int hw4  = blockIdx.x * TPB + tid;   // [0, HWSZ/4)

    __shared__ float s_gw[NUM_OP], s_bw[NUM_OP];
    __shared__ float s_wrsum, s_br;

    // 1) Issue the 6 semantic loads immediately (independent of coefficients).
    const float4* semb =
        reinterpret_cast<const float4*>(sem + (size_t)b * SEM_CH * HWSZ + 2 * HWSZ) + hw4;
    float4 sv[NUM_OP];
#pragma unroll
    for (int k = 0; k < NUM_OP; ++k)
        sv[k] = __ldg(semb + (size_t)k * (HWSZ / 4));

    // 2) Fold runs while those LDGs are in flight (warps 0-6 of 16).
    if (warp < NUM_OP) {
        const int k = warp;
        const float4 a  = g_actv4[b][lane];
        const float4 wg = reinterpret_cast<const float4*>(Wg)[(size_t)k * (NHIDDEN / 4) + lane];
        const float4 wb = reinterpret_cast<const float4*>(Wb)[(size_t)k * (NHIDDEN / 4) + lane];
        float pg = dot4(a, wg);
        float pb = dot4(a, wb);
#pragma unroll
        for (int off = 16; off > 0; off >>= 1) {
            pg += __shfl_xor_sync(0xFFFFFFFFu, pg, off);
            pb += __shfl_xor_sync(0xFFFFFFFFu, pb, off);
        }
        if (lane == 0) {
            const float wr = Wr[k];
            s_gw[k] = (pg + bg[k]) * wr;
            s_bw[k] = (pb + bb[k]) * wr;
        }
    } else if (warp == 6 && lane == 0) {
        float s = 0.0f;
#pragma unroll
        for (int k = 0; k < NUM_OP; ++k) s += Wr[k];
        s_wrsum = s;
        s_br = br[0];
    }
    __syncthreads();   // drains smem stores; outstanding LDGs keep flying

    // 3) Combine (first consumption of sv -> scoreboard wait lands here).
    float4 scale = make_float4(s_wrsum, s_wrsum, s_wrsum, s_wrsum);
    float4 shift = make_float4(s_br, s_br, s_br, s_br);
#pragma unroll
    for (int k = 0; k < NUM_OP; ++k) {
        const float gw = s_gw[k];
        const float bw = s_bw[k];
        scale.x += gw * sv[k].x;  scale.y += gw * sv[k].y;
        scale.z += gw * sv[k].z;  scale.w += gw * sv[k].w;
        shift.x += bw * sv[k].x;  shift.y += bw * sv[k].y;
        shift.z += bw * sv[k].z;  shift.w += bw * sv[k].w;
    }

    // 4) Stream 16 channels of x -> out; 8 KB contiguous per channel per block.
    const float4* xb = reinterpret_cast<const float4*>(x + (size_t)b * NC * HWSZ) + hw4;
    float4*       ob = reinterpret_cast<float4*>(out + (size_t)b * NC * HWSZ) + hw4;

#pragma unroll 8
    for (int c = c0; c < c0 + CCHUNK; ++c) {
        float4 xv = xb[(size_t)c * (HWSZ / 4)];
        float4 o;
        o.x = xv.x * scale.x + shift.x;
        o.y = xv.y * scale.y + shift.y;
        o.z = xv.z * scale.z + shift.z;
        o.w = xv.w * scale.w + shift.w;
        ob[(size_t)c * (HWSZ / 4)] = o;
    }
}

// ---------------------------------------------------------------------------
extern "C" void kernel_launch(void* const* d_in, const int* in_sizes, int n_in,
                              void* d_out, int out_size) {
    const float* x    = (const float*)d_in[0];
    const float* lang = (const float*)d_in[1];
    const float* sem  = (const float*)d_in[2];
    const float* Ws   = (const float*)d_in[3];
    const float* bs   = (const float*)d_in[4];
    const float* Wg   = (const float*)d_in[5];
    const float* bg   = (const float*)d_in[6];
    const float* Wb   = (const float*)d_in[7];
    const float* bb   = (const float*)d_in[8];
    const float* Wr   = (const float*)d_in[9];
    const float* br   = (const float*)d_in[10];
    float* out = (float*)d_out;

    actv_kernel<<<32, 256>>>(lang, Ws, bs);

    dim3 grid(GRID_X, NB, GRID_Z);
    main_kernel<<<grid, TPB>>>(x, sem, Wg, bg, Wb, bb, Wr, br, out);
}